// round 14
// baseline (speedup 1.0000x reference)
#include <cuda_runtime.h>
#include <math.h>

#define HEIGHT 1024
#define WIDTH  2048
#define PPT 4      // pixels per thread (4 | 2048, float4 aligned)
#define TPB 256

// ---------------------------------------------------------------------------
// Compile-time trig tables (R13): replicate the reference grid EXACTLY at
// float32 granularity; sin/cos in constexpr double (Taylor + reflection).
// ---------------------------------------------------------------------------
constexpr double PI_D = 3.141592653589793238462643383279502884;

constexpr double ksin0(double x) {           // |x| <= pi/2
    const double x2 = x * x;
    double t = x, s = x;
    for (int k = 1; k <= 13; ++k) {
        t *= -x2 / (double)((2 * k) * (2 * k + 1));
        s += t;
    }
    return s;
}
constexpr double kcos0(double x) {           // |x| <= pi/2
    const double x2 = x * x;
    double t = 1.0, s = 1.0;
    for (int k = 1; k <= 13; ++k) {
        t *= -x2 / (double)((2 * k - 1) * (2 * k));
        s += t;
    }
    return s;
}
constexpr double ksin(double x) {            // |x| <= pi
    const double ax = x < 0 ? -x : x;
    const double s  = (ax > PI_D * 0.5) ? ksin0(PI_D - ax) : ksin0(ax);
    return x < 0 ? -s : s;
}
constexpr double kcos(double x) {            // |x| <= pi
    const double ax = x < 0 ? -x : x;
    return (ax > PI_D * 0.5) ? -kcos0(PI_D - ax) : kcos0(ax);
}

struct Tables {
    alignas(16) float sth[HEIGHT];
    alignas(16) float cth[HEIGHT];
    alignas(16) float sph[WIDTH];
    alignas(16) float cph[WIDTH];
};

constexpr Tables make_tables() {
    Tables t{};
    for (int i = 0; i < HEIGHT; ++i) {
        const float gx = -1.0f + (float)i * (2.0f / (float)HEIGHT);   // exact
        const float pm = gx * 1.5707963267948966f;                    // fl32 mul
        const float th = pm + 1.5707963267948966f;                    // fl32 add
        t.sth[i] = (float)ksin((double)th);
        t.cth[i] = (float)kcos((double)th);
    }
    for (int j = 0; j < WIDTH; ++j) {
        const float gy = -1.0f + (float)j * (2.0f / (float)WIDTH);    // exact
        const float ph = gy * 3.14159265358979323846f;                // fl32 mul
        t.sph[j] = (float)ksin((double)ph);
        t.cph[j] = (float)kcos((double)ph);
    }
    return t;
}

__device__ constexpr Tables g_tables = make_tables();

// ---------------------------------------------------------------------------

__device__ __forceinline__ float fsqrt_approx(float x) {
    float r;
    asm("sqrt.approx.f32 %0, %1;" : "=f"(r) : "f"(x));
    return r;
}

__global__ void __launch_bounds__(TPB)
depth3dgrid_kernel(const float* __restrict__ depth,
                   const float* __restrict__ trans,
                   float* __restrict__ out)
{
    // Block-uniform geometry: each block = 1024 consecutive pixels = half a row.
    const int b  = blockIdx.y;
    const int hr = blockIdx.x >> 1;                         // row (uniform)
    const int w0 = ((blockIdx.x & 1) << 10) + threadIdx.x * PPT;
    const int base = hr * WIDTH + w0;                       // pixel idx in batch

    // Pre-scaled transform: sC[0..3]=s_th*T0j, [4..7]=s_th*T1j,
    // [8..11]=c_th*T2j, [12..15]=T3j  -- computed ONCE per block (was 9
    // FMUL + 2 LDG in every thread).  Same FMUL.RN values as R12/R13.
    __shared__ float sC[16];
    if (threadIdx.x < 16) {
        const float tv = trans[b * 16 + threadIdx.x];
        const int   r  = threadIdx.x >> 2;
        const float s_th = g_tables.sth[hr];
        const float c_th = g_tables.cth[hr];
        const float m = (r < 2) ? s_th : ((r == 2) ? c_th : 1.0f);
        sC[threadIdx.x] = tv * m;
    }
    __syncthreads();

    const float a0 = sC[0],  a1 = sC[1],  a2 = sC[2];
    const float b0 = sC[4],  b1 = sC[5],  b2 = sC[6];
    const float k0 = sC[8],  k1 = sC[9],  k2 = sC[10];
    const float T30 = sC[12], T31 = sC[13], T32 = sC[14];

    const float4 cpv = *(const float4*)&g_tables.cph[w0];
    const float4 spv = *(const float4*)&g_tables.sph[w0];
    const float4 dv  = *(const float4*)(depth + (size_t)b * (HEIGHT * WIDTH) + base);

    const float cpa[4] = {cpv.x, cpv.y, cpv.z, cpv.w};
    const float spa[4] = {spv.x, spv.y, spv.z, spv.w};
    const float dd[4]  = {dv.x,  dv.y,  dv.z,  dv.w};

    float res[8];
#pragma unroll
    for (int k = 0; k < 4; ++k) {
        const float cp = cpa[k], sp = spa[k], d = dd[k];

        // transform (bit-identical fma chain to R12/R13 -- sign-critical)
        const float px = fmaf(d, fmaf(cp, a0, fmaf(sp, b0, k0)), T30);
        const float py = fmaf(d, fmaf(cp, a1, fmaf(sp, b1, k1)), T31);
        const float pz = fmaf(d, fmaf(cp, a2, fmaf(sp, b2, k2)), T32);

        // t = pz / (sqrt(s2) + 1e-4) via rsqrt + first-order expansion
        const float s2  = fmaf(px, px, fmaf(py, py, fmaf(pz, pz, 1e-30f)));
        const float ris = rsqrtf(s2);
        const float pr  = pz * ris;
        const float t   = fmaf(pr * ris, -1e-4f, pr);

        // theta = acos(t)*2/pi - 1, 2/pi folded into P3; sign via XOR
        const float xa = fabsf(t);
        float p = fmaf(xa, -0.0119235f, 0.0472755f);
        p = fmaf(p, xa, -0.1350346f);
        p = fmaf(p, xa,  0.9999573f);
        const float sq = fsqrt_approx(fmaxf(1.0f - xa, 1e-30f));
        const float v  = fmaf(p, sq, -1.0f);
        const float theta_o = __int_as_float(__float_as_int(v) ^
                                 (__float_as_int(t) & 0x80000000));

        // phi = atan2(py, px)/pi, 1/pi folded into P9 (Estrin form);
        // quadrant fixes 0.5-q / 1-q (select structure unchanged)
        const float ax = fabsf(px), ay = fabsf(py);
        const float mx = fmaxf(fmaxf(ax, ay), 1e-37f);
        const float mn = fminf(ax, ay);
        const float a   = __fdividef(mn, mx);
        const float ss  = a * a;
        const float ss2 = ss * ss;
        const float e0  = fmaf(ss, -0.10513979f, 0.31826722f); // c1*ss + c0
        const float e1  = fmaf(ss,  0.00663209f, -0.02709852f);// c4*ss + c3
        const float e2  = fmaf(ss2, e1, 0.05734683f);          // + c2
        float q = fmaf(ss2, e2, e0);
        q = q * a;                                     // atan(mn/mx)/pi
        q = (ay > ax)   ? (0.5f - q) : q;
        q = (px < 0.0f) ? (1.0f - q) : q;
        const float phi_o = copysignf(q, py);

        res[2 * k]     = phi_o;    // channel 0 = phi
        res[2 * k + 1] = theta_o;  // channel 1 = theta
    }

    float4* optr = (float4*)(out + ((size_t)b * (HEIGHT * WIDTH) + base) * 2);
    optr[0] = make_float4(res[0], res[1], res[2], res[3]);
    optr[1] = make_float4(res[4], res[5], res[6], res[7]);
}

extern "C" void kernel_launch(void* const* d_in, const int* in_sizes, int n_in,
                              void* d_out, int out_size)
{
    const float* depth = (const float*)d_in[0];   // (4,1024,2048,1) f32
    const float* trans = (const float*)d_in[1];   // (4,4,4) f32
    float* out = (float*)d_out;                   // (4,1024,2048,2) f32

    dim3 grid(HEIGHT * WIDTH / (TPB * PPT), 4, 1); // (2048, 4)
    depth3dgrid_kernel<<<grid, TPB>>>(depth, trans, out);
}